// round 10
// baseline (speedup 1.0000x reference)
#include <cuda_runtime.h>
#include <cfloat>

#define HW   (512*512)
#define W    512
#define NCH  48            // 16 batches * 3 channels
#define FW   23
#define PAD  11

#define PB   8192          // pct histogram bins: i=(int)(res*256)+4096, res in (-16,16)
#define CAP  16384         // median candidate capacity per channel
#define SEG  8             // data-pass blocks per channel
// median fast-path candidate window in value space: [-10/512, +10/512)
#define T_LO (-10.0f/512.0f)
#define T_HI ( 10.0f/512.0f)

// conv tiling: 64x32 tile, 256 threads, 4 CTAs/SM (regs 58*1024=59K<64K, smem 4*47.7K=191K<228K)
#define CTX  64
#define CTY  32
#define CSH  (CTX + 2*PAD)   // 86 (cols incl halo)
#define CSHY (CTY + 2*PAD)   // 54 (rows incl halo)
#define CTHREADS 256
// dynamic smem: s_in + s_tmp (floats) + packed u16 hist (PB/2 words)
#define CONV_SMEM ((CSHY*CSH + CSHY*CTX + PB/2) * 4)

// scratch (no cudaMalloc allowed; zero-initialized at load, kernels restore zeros)
__device__ float    g_res[(size_t)NCH * HW];
__device__ unsigned g_phist[NCH * PB];
__device__ float    g_cand[NCH * CAP];
__device__ int      g_ccount[NCH];
__device__ int      g_below[NCH];
__device__ float    g_med[NCH];
__device__ float    g_lo[NCH];
__device__ float    g_hi[NCH];
__device__ float    g_k1[FW];

// ---------------------------------------------------------------------------
// block-wide exclusive scan over 1024 threads (shuffle-based)
// ---------------------------------------------------------------------------
__device__ __forceinline__ unsigned block_excl_scan_1024(unsigned val) {
    __shared__ unsigned warpsum[32];
    const unsigned lane = threadIdx.x & 31, wid = threadIdx.x >> 5;
    unsigned s = val;
    #pragma unroll
    for (int o = 1; o < 32; o <<= 1) {
        unsigned t = __shfl_up_sync(0xFFFFFFFFu, s, o);
        if (lane >= o) s += t;
    }
    if (lane == 31) warpsum[wid] = s;
    __syncthreads();
    if (wid == 0) {
        unsigned w = warpsum[lane];
        #pragma unroll
        for (int o = 1; o < 32; o <<= 1) {
            unsigned t = __shfl_up_sync(0xFFFFFFFFu, w, o);
            if (lane >= o) w += t;
        }
        warpsum[lane] = w;
    }
    __syncthreads();
    unsigned wexcl = wid ? warpsum[wid - 1] : 0u;
    return wexcl + s - val;
}

__device__ __forceinline__ int med_bin(float v) {   // for fallback only
    int b = (int)floorf(fmaf(v, 512.0f, 4096.0f));
    return b < 0 ? 0 : (b > 8191 ? 8191 : b);
}

// ---------------------------------------------------------------------------
// launch #1 (tiny): k1 = row sums of 2D gaussian kernel
// ---------------------------------------------------------------------------
__global__ void k1_prep(const float* __restrict__ kern) {
    int i = threadIdx.x;
    if (i < FW) {
        float s = 0.0f;
        for (int j = 0; j < FW; j++) s += kern[i * FW + j];
        g_k1[i] = s;
    }
}

// ---------------------------------------------------------------------------
// launch #2: count values below window + collect window candidates
// ---------------------------------------------------------------------------
__global__ __launch_bounds__(512)
void med_count(const float* __restrict__ x) {
    const int ch = blockIdx.x / SEG, seg = blockIdx.x % SEG;
    const int tid = threadIdx.x;
    const float4* p = (const float4*)(x + (size_t)ch * HW) + (size_t)seg * (HW / 4 / SEG);
    int below = 0;
    for (int i = tid; i < HW / 4 / SEG; i += 512) {
        float4 v = p[i];
        float vv[4] = { v.x, v.y, v.z, v.w };
        #pragma unroll
        for (int j = 0; j < 4; j++) {
            float f = vv[j];
            below += (f < T_LO);
            if (f >= T_LO && f < T_HI) {
                int pp = atomicAdd(&g_ccount[ch], 1);
                if (pp < CAP) g_cand[ch * CAP + pp] = f;
            }
        }
    }
    // warp-aggregate then one global atomic per warp
    for (int o = 16; o; o >>= 1) below += __shfl_down_sync(0xFFFFFFFFu, below, o);
    if ((tid & 31) == 0 && below) atomicAdd(&g_below[ch], below);
}

// ---------------------------------------------------------------------------
// launch #3: exact median selection (fast path via window; exact fallback)
// ---------------------------------------------------------------------------
__global__ __launch_bounds__(1024)
void med_sel(const float* __restrict__ x) {
    const int ch = blockIdx.x, tid = threadIdx.x;
    __shared__ unsigned fh[8192];                     // 32 KB (coarse or fine hist)
    __shared__ float s_red[32];
    __shared__ float s_mn, s_mx;
    __shared__ int s_fb, s_r2, s_n, s_k2;
    __shared__ int s_cnt;
    __shared__ float mem[512];
    __shared__ int mcount;

    const int k = (HW - 1) / 2;
    int below = g_below[ch];
    int cnt   = g_ccount[ch];
    __syncthreads();
    if (tid == 0) {                                   // restore for next replay
        g_below[ch] = 0;
        g_ccount[ch] = 0;
        s_cnt = 0;
    }
    const bool fast = (below <= k) && (k < below + cnt) && (cnt <= CAP);

    if (fast) {
        if (tid == 0) { s_n = cnt; s_k2 = k - below; }
        __syncthreads();
    } else {
        // ---- exact fallback (rare): coarse hist over channel, then collect ----
        for (int i = tid; i < 8192; i += 1024) fh[i] = 0;
        __syncthreads();
        const float4* p = (const float4*)(x + (size_t)ch * HW);
        for (int i = tid; i < HW / 4; i += 1024) {
            float4 v = p[i];
            atomicAdd(&fh[med_bin(v.x)], 1u);
            atomicAdd(&fh[med_bin(v.y)], 1u);
            atomicAdd(&fh[med_bin(v.z)], 1u);
            atomicAdd(&fh[med_bin(v.w)], 1u);
        }
        __syncthreads();
        unsigned loc[8];
        unsigned s = 0;
        #pragma unroll
        for (int j = 0; j < 8; j++) { loc[j] = fh[tid * 8 + j]; s += loc[j]; }
        unsigned pref = block_excl_scan_1024(s);
        __shared__ int s_selbin;
        if (pref <= (unsigned)k && (unsigned)k < pref + s) {
            unsigned cum = pref;
            #pragma unroll
            for (int j = 0; j < 8; j++) {
                unsigned c = loc[j];
                if (cum + c > (unsigned)k) { s_selbin = tid * 8 + j; s_k2 = (int)(k - cum); break; }
                cum += c;
            }
        }
        __syncthreads();
        const int sb = s_selbin;
        for (int i = tid; i < HW / 4; i += 1024) {
            float4 v = p[i];
            float vv[4] = { v.x, v.y, v.z, v.w };
            #pragma unroll
            for (int j = 0; j < 4; j++) {
                if (med_bin(vv[j]) == sb) {
                    int pp = atomicAdd(&s_cnt, 1);
                    if (pp < CAP) g_cand[ch * CAP + pp] = vv[j];
                }
            }
        }
        __syncthreads();
        if (tid == 0) s_n = s_cnt < CAP ? s_cnt : CAP;
        __syncthreads();
    }

    const int n = s_n, k2 = s_k2;
    const float* c = g_cand + ch * CAP;

    // ---- min/max reduce over candidates ----
    float mn = FLT_MAX, mx = -FLT_MAX;
    for (int i = tid; i < n; i += 1024) {
        float v = c[i];
        mn = fminf(mn, v); mx = fmaxf(mx, v);
    }
    for (int o = 16; o; o >>= 1) {
        mn = fminf(mn, __shfl_down_sync(0xFFFFFFFFu, mn, o));
        mx = fmaxf(mx, __shfl_down_sync(0xFFFFFFFFu, mx, o));
    }
    if ((tid & 31) == 0) s_red[tid >> 5] = mn;
    __syncthreads();
    if (tid < 32) {
        float v = s_red[tid];
        for (int o = 16; o; o >>= 1) v = fminf(v, __shfl_down_sync(0xFFFFFFFFu, v, o));
        if (tid == 0) s_mn = v;
    }
    __syncthreads();
    if ((tid & 31) == 0) s_red[tid >> 5] = mx;
    __syncthreads();
    if (tid < 32) {
        float v = s_red[tid];
        for (int o = 16; o; o >>= 1) v = fmaxf(v, __shfl_down_sync(0xFFFFFFFFu, v, o));
        if (tid == 0) s_mx = v;
    }
    __syncthreads();
    const float mnv = s_mn, mxv = s_mx;
    if (mnv == mxv) { if (tid == 0) g_med[ch] = mnv + 0.2f; return; }

    // ---- fine histogram over candidates ----
    for (int i = tid; i < 8192; i += 1024) fh[i] = 0;
    __syncthreads();
    const float scale = 8192.0f / (mxv - mnv);
    for (int i = tid; i < n; i += 1024) {
        int b = (int)((c[i] - mnv) * scale);
        b = b < 0 ? 0 : (b > 8191 ? 8191 : b);
        atomicAdd(&fh[b], 1u);
    }
    __syncthreads();
    unsigned loc[8];
    unsigned s = 0;
    #pragma unroll
    for (int j = 0; j < 8; j++) { loc[j] = fh[tid * 8 + j]; s += loc[j]; }
    unsigned pref = block_excl_scan_1024(s);
    if (pref <= (unsigned)k2 && (unsigned)k2 < pref + s) {
        unsigned cum = pref;
        #pragma unroll
        for (int j = 0; j < 8; j++) {
            unsigned cc = loc[j];
            if (cum + cc > (unsigned)k2) { s_fb = tid * 8 + j; s_r2 = (int)(k2 - cum); break; }
            cum += cc;
        }
    }
    if (tid == 0) mcount = 0;
    __syncthreads();
    const int fb = s_fb, r2 = s_r2;
    for (int i = tid; i < n; i += 1024) {
        int b = (int)((c[i] - mnv) * scale);
        b = b < 0 ? 0 : (b > 8191 ? 8191 : b);
        if (b == fb) {
            int pp = atomicAdd(&mcount, 1);
            if (pp < 512) mem[pp] = c[i];
        }
    }
    __syncthreads();
    int m = mcount < 512 ? mcount : 512;
    for (int i = tid; i < m; i += 1024) {
        float vi = mem[i];
        int r = 0;
        for (int j = 0; j < m; j++) {
            float vj = mem[j];
            r += (vj < vi) || (vj == vi && j < i);
        }
        if (r == r2) g_med[ch] = vi + 0.2f;
    }
}

// ---------------------------------------------------------------------------
// launch #4 (profiled slot): separable conv (sliding-window, 8 outputs/thread)
// + fused pct hist packed 2 x u16 (max 2048 counts/block, no carry risk)
// 256 threads, 64x32 tile, 47.7 KB smem -> 4 CTAs/SM
// ---------------------------------------------------------------------------
__global__ __launch_bounds__(CTHREADS, 4)
void conv_kernel(const float* __restrict__ x, const float* __restrict__ mask) {
    extern __shared__ float dsm[];
    float*    s_in  = dsm;                          // CSHY * CSH
    float*    s_tmp = dsm + CSHY * CSH;             // CSHY * CTX
    unsigned* s_h   = (unsigned*)(dsm + CSHY * CSH + CSHY * CTX);  // PB/2 packed
    __shared__ float s_k[FW];

    const int tid = threadIdx.x;
    const int ch = blockIdx.z;
    const int nb = ch / 3;
    const int bx = blockIdx.x * CTX, by = blockIdx.y * CTY;

    if (tid < FW) s_k[tid] = g_k1[tid];
    for (int i = tid; i < PB / 2; i += CTHREADS) s_h[i] = 0;

    const float* xc = x + (size_t)ch * HW;
    const float* mc = mask + (size_t)nb * HW;
    const float med = g_med[ch];

    for (int i = tid; i < CSHY * CSH; i += CTHREADS) {
        int r = i / CSH, c = i % CSH;
        int gy = min(max(by - PAD + r, 0), 511);
        int gx = min(max(bx - PAD + c, 0), 511);
        float xv = xc[gy * W + gx];
        float mv = mc[gy * W + gx];
        s_in[r * CSH + c] = mv * xv + (1.0f - mv) * med;
    }
    __syncthreads();

    // horizontal pass: CSHY rows x 8 groups of 8 outputs = 432 items
    for (int item = tid; item < CSHY * (CTX / 8); item += CTHREADS) {
        const int r = item >> 3, g = item & 7;
        const float* row = s_in + r * CSH + g * 8;
        float w[8], acc[8];
        #pragma unroll
        for (int m = 0; m < 8; m++) { w[m] = row[m]; acc[m] = 0.0f; }
        #pragma unroll
        for (int t = 0; t < FW; t++) {
            const float kt = s_k[t];
            #pragma unroll
            for (int m = 0; m < 8; m++) acc[m] = fmaf(w[m], kt, acc[m]);
            if (t < FW - 1) {
                #pragma unroll
                for (int m = 0; m < 7; m++) w[m] = w[m + 1];
                w[7] = row[t + 8];
            }
        }
        float* outp = s_tmp + r * CTX + g * 8;
        #pragma unroll
        for (int m = 0; m < 8; m++) outp[m] = acc[m];
    }
    __syncthreads();

    // vertical pass: 64 cols x 4 y-groups of 8 outputs = 256 items (1/thread)
    {
        const int xx = tid & 63, y0 = (tid >> 6) * 8;
        const float* col = s_tmp + y0 * CTX + xx;
        float w[8], acc[8];
        #pragma unroll
        for (int m = 0; m < 8; m++) { w[m] = col[m * CTX]; acc[m] = 0.0f; }
        #pragma unroll
        for (int t = 0; t < FW; t++) {
            const float kt = s_k[t];
            #pragma unroll
            for (int m = 0; m < 8; m++) acc[m] = fmaf(w[m], kt, acc[m]);
            if (t < FW - 1) {
                #pragma unroll
                for (int m = 0; m < 7; m++) w[m] = w[m + 1];
                w[7] = col[(t + 8) * CTX];
            }
        }
        float* rp = g_res + (size_t)ch * HW + (size_t)(by + y0) * W + bx + xx;
        #pragma unroll
        for (int m = 0; m < 8; m++) {
            float xp = s_in[(y0 + m + PAD) * CSH + (xx + PAD)];
            float rv = 4.0f * (xp - acc[m]);
            rp[m * W] = rv;
            int b = (int)(rv * 256.0f) + PB / 2;
            b = b < 0 ? 0 : (b > PB - 1 ? PB - 1 : b);
            atomicAdd(&s_h[b >> 1], 1u << ((b & 1) * 16));
        }
    }
    __syncthreads();

    // flush fused percentile histogram (unpack u16 pairs)
    unsigned* gh = g_phist + ch * PB;
    for (int i = tid; i < PB / 2; i += CTHREADS) {
        unsigned w = s_h[i];
        unsigned lo = w & 0xFFFFu, hi = w >> 16;
        if (lo) atomicAdd(&gh[2 * i], lo);
        if (hi) atomicAdd(&gh[2 * i + 1], hi);
    }
}

// ---------------------------------------------------------------------------
// launch #5: extract lo/hi percentiles, restore hist to zero
// ---------------------------------------------------------------------------
__global__ __launch_bounds__(1024)
void pct_scan() {
    const int ch = blockIdx.x, tid = threadIdx.x;
    unsigned* h = g_phist + ch * PB;
    unsigned loc[PB / 1024];
    unsigned s = 0;
    #pragma unroll
    for (int j = 0; j < PB / 1024; j++) { loc[j] = h[tid * (PB / 1024) + j]; s += loc[j]; }
    unsigned pref = block_excl_scan_1024(s);

    const double n1 = (double)(HW - 1);
    #pragma unroll
    for (int rsel = 0; rsel < 2; rsel++) {
        double pos = n1 * (rsel ? 0.97 : 0.03);
        unsigned k = (unsigned)pos;
        float fr = (float)(pos - (double)k);
        if (pref <= k && k < pref + s) {
            unsigned cum = pref;
            #pragma unroll
            for (int j = 0; j < PB / 1024; j++) {
                unsigned c = loc[j];
                int b = tid * (PB / 1024) + j;
                if (cum + c > k) {
                    float v = (float)(b - PB / 2) * (1.0f / 256.0f);
                    float v1 = v;
                    if (k + 1 >= cum + c) {               // next value in a later bin
                        int b2 = b + 1;
                        while (b2 < PB && h[b2] == 0) b2++;
                        if (b2 < PB) v1 = (float)(b2 - PB / 2) * (1.0f / 256.0f);
                    }
                    float out = v + fr * (v1 - v);
                    if (rsel) g_hi[ch] = out; else g_lo[ch] = out;
                    break;
                }
                cum += c;
            }
        }
    }
    __syncthreads();
    // restore histogram to zero for the next replay
    #pragma unroll
    for (int j = 0; j < PB / 1024; j++) h[tid * (PB / 1024) + j] = 0u;
}

// ---------------------------------------------------------------------------
// launch #6: normalize + mask
// ---------------------------------------------------------------------------
__global__ __launch_bounds__(512)
void final_kernel(const float* __restrict__ mask, float* __restrict__ out) {
    const int ch = blockIdx.y;
    const int nb = ch / 3;
    const int i = blockIdx.x * blockDim.x + threadIdx.x;   // float4 index
    const float lo = g_lo[ch], hi = g_hi[ch];
    const float inv = 1.0f / (hi - lo);
    float4 r = ((const float4*)(g_res + (size_t)ch * HW))[i];
    float4 m = ((const float4*)(mask + (size_t)nb * HW))[i];
    float4 o;
    o.x = (r.x - lo) * inv * m.x;
    o.y = (r.y - lo) * inv * m.y;
    o.z = (r.z - lo) * inv * m.z;
    o.w = (r.w - lo) * inv * m.w;
    ((float4*)out)[(size_t)ch * (HW / 4) + i] = o;
}

// ---------------------------------------------------------------------------
extern "C" void kernel_launch(void* const* d_in, const int* in_sizes, int n_in,
                              void* d_out, int out_size) {
    const float* x    = (const float*)d_in[0];
    const float* mask = (const float*)d_in[1];
    const float* kern = (const float*)d_in[2];
    float* out = (float*)d_out;

    cudaFuncSetAttribute(conv_kernel, cudaFuncAttributeMaxDynamicSharedMemorySize, CONV_SMEM);

    k1_prep<<<1, 32>>>(kern);
    med_count<<<NCH * SEG, 512>>>(x);
    med_sel<<<NCH, 1024>>>(x);
    conv_kernel<<<dim3(W / CTX, W / CTY, NCH), CTHREADS, CONV_SMEM>>>(x, mask);
    pct_scan<<<NCH, 1024>>>();
    final_kernel<<<dim3(HW / 4 / 512, NCH), 512>>>(mask, out);
}

// round 11
// speedup vs baseline: 1.4239x; 1.4239x over previous
#include <cuda_runtime.h>
#include <cfloat>

#define HW   (512*512)
#define W    512
#define NCH  48            // 16 batches * 3 channels
#define FW   23
#define PAD  11

#define PB   8192          // pct histogram bins: i=(int)(res*256)+4096, res in (-16,16)
#define CAP  16384         // median candidate capacity per channel
#define SEG  8             // data-pass blocks per channel
// median fast-path candidate window in value space: [-10/512, +10/512)
#define T_LO (-10.0f/512.0f)
#define T_HI ( 10.0f/512.0f)

// conv tiling: r8-proven 64x64, 512 threads, 2 CTAs/SM
#define CTX  64
#define CTY  64
#define CSH  (CTX + 2*PAD)   // 86
#define CTHREADS 512
// dynamic smem: s_in + s_tmp (floats) + packed u16 hist (PB/2 words) = 66.4 KB
#define CONV_SMEM ((CSH*CSH + CSH*CTX + PB/2) * 4)

// scratch (no cudaMalloc allowed; zero-initialized at load, kernels restore zeros)
__device__ float    g_res[(size_t)NCH * HW];
__device__ unsigned g_phist[NCH * PB];
__device__ float    g_cand[NCH * CAP];
__device__ int      g_ccount[NCH];
__device__ int      g_below[NCH];
__device__ float    g_med[NCH];
__device__ float    g_lo[NCH];
__device__ float    g_hi[NCH];
__device__ float    g_k1[FW];

// ---------------------------------------------------------------------------
// block-wide exclusive scan over 1024 threads (shuffle-based)
// ---------------------------------------------------------------------------
__device__ __forceinline__ unsigned block_excl_scan_1024(unsigned val) {
    __shared__ unsigned warpsum[32];
    const unsigned lane = threadIdx.x & 31, wid = threadIdx.x >> 5;
    unsigned s = val;
    #pragma unroll
    for (int o = 1; o < 32; o <<= 1) {
        unsigned t = __shfl_up_sync(0xFFFFFFFFu, s, o);
        if (lane >= o) s += t;
    }
    if (lane == 31) warpsum[wid] = s;
    __syncthreads();
    if (wid == 0) {
        unsigned w = warpsum[lane];
        #pragma unroll
        for (int o = 1; o < 32; o <<= 1) {
            unsigned t = __shfl_up_sync(0xFFFFFFFFu, w, o);
            if (lane >= o) w += t;
        }
        warpsum[lane] = w;
    }
    __syncthreads();
    unsigned wexcl = wid ? warpsum[wid - 1] : 0u;
    return wexcl + s - val;
}

__device__ __forceinline__ int med_bin(float v) {   // for fallback only
    int b = (int)floorf(fmaf(v, 512.0f, 4096.0f));
    return b < 0 ? 0 : (b > 8191 ? 8191 : b);
}

// ---------------------------------------------------------------------------
// launch #1 (tiny): k1 = row sums of 2D gaussian kernel
// ---------------------------------------------------------------------------
__global__ void k1_prep(const float* __restrict__ kern) {
    int i = threadIdx.x;
    if (i < FW) {
        float s = 0.0f;
        for (int j = 0; j < FW; j++) s += kern[i * FW + j];
        g_k1[i] = s;
    }
}

// ---------------------------------------------------------------------------
// launch #2: count values below window + collect window candidates
// ---------------------------------------------------------------------------
__global__ __launch_bounds__(512)
void med_count(const float* __restrict__ x) {
    const int ch = blockIdx.x / SEG, seg = blockIdx.x % SEG;
    const int tid = threadIdx.x;
    const float4* p = (const float4*)(x + (size_t)ch * HW) + (size_t)seg * (HW / 4 / SEG);
    int below = 0;
    for (int i = tid; i < HW / 4 / SEG; i += 512) {
        float4 v = p[i];
        float vv[4] = { v.x, v.y, v.z, v.w };
        #pragma unroll
        for (int j = 0; j < 4; j++) {
            float f = vv[j];
            below += (f < T_LO);
            if (f >= T_LO && f < T_HI) {
                int pp = atomicAdd(&g_ccount[ch], 1);
                if (pp < CAP) g_cand[ch * CAP + pp] = f;
            }
        }
    }
    // warp-aggregate then one global atomic per warp
    for (int o = 16; o; o >>= 1) below += __shfl_down_sync(0xFFFFFFFFu, below, o);
    if ((tid & 31) == 0 && below) atomicAdd(&g_below[ch], below);
}

// ---------------------------------------------------------------------------
// launch #3: exact median selection (fast path via window; exact fallback)
// ---------------------------------------------------------------------------
__global__ __launch_bounds__(1024)
void med_sel(const float* __restrict__ x) {
    const int ch = blockIdx.x, tid = threadIdx.x;
    __shared__ unsigned fh[8192];                     // 32 KB (coarse or fine hist)
    __shared__ float s_red[32];
    __shared__ float s_mn, s_mx;
    __shared__ int s_fb, s_r2, s_n, s_k2;
    __shared__ int s_cnt;
    __shared__ float mem[512];
    __shared__ int mcount;

    const int k = (HW - 1) / 2;
    int below = g_below[ch];
    int cnt   = g_ccount[ch];
    __syncthreads();
    if (tid == 0) {                                   // restore for next replay
        g_below[ch] = 0;
        g_ccount[ch] = 0;
        s_cnt = 0;
    }
    const bool fast = (below <= k) && (k < below + cnt) && (cnt <= CAP);

    if (fast) {
        if (tid == 0) { s_n = cnt; s_k2 = k - below; }
        __syncthreads();
    } else {
        // ---- exact fallback (rare): coarse hist over channel, then collect ----
        for (int i = tid; i < 8192; i += 1024) fh[i] = 0;
        __syncthreads();
        const float4* p = (const float4*)(x + (size_t)ch * HW);
        for (int i = tid; i < HW / 4; i += 1024) {
            float4 v = p[i];
            atomicAdd(&fh[med_bin(v.x)], 1u);
            atomicAdd(&fh[med_bin(v.y)], 1u);
            atomicAdd(&fh[med_bin(v.z)], 1u);
            atomicAdd(&fh[med_bin(v.w)], 1u);
        }
        __syncthreads();
        unsigned loc[8];
        unsigned s = 0;
        #pragma unroll
        for (int j = 0; j < 8; j++) { loc[j] = fh[tid * 8 + j]; s += loc[j]; }
        unsigned pref = block_excl_scan_1024(s);
        __shared__ int s_selbin;
        if (pref <= (unsigned)k && (unsigned)k < pref + s) {
            unsigned cum = pref;
            #pragma unroll
            for (int j = 0; j < 8; j++) {
                unsigned c = loc[j];
                if (cum + c > (unsigned)k) { s_selbin = tid * 8 + j; s_k2 = (int)(k - cum); break; }
                cum += c;
            }
        }
        __syncthreads();
        const int sb = s_selbin;
        for (int i = tid; i < HW / 4; i += 1024) {
            float4 v = p[i];
            float vv[4] = { v.x, v.y, v.z, v.w };
            #pragma unroll
            for (int j = 0; j < 4; j++) {
                if (med_bin(vv[j]) == sb) {
                    int pp = atomicAdd(&s_cnt, 1);
                    if (pp < CAP) g_cand[ch * CAP + pp] = vv[j];
                }
            }
        }
        __syncthreads();
        if (tid == 0) s_n = s_cnt < CAP ? s_cnt : CAP;
        __syncthreads();
    }

    const int n = s_n, k2 = s_k2;
    const float* c = g_cand + ch * CAP;

    // ---- min/max reduce over candidates ----
    float mn = FLT_MAX, mx = -FLT_MAX;
    for (int i = tid; i < n; i += 1024) {
        float v = c[i];
        mn = fminf(mn, v); mx = fmaxf(mx, v);
    }
    for (int o = 16; o; o >>= 1) {
        mn = fminf(mn, __shfl_down_sync(0xFFFFFFFFu, mn, o));
        mx = fmaxf(mx, __shfl_down_sync(0xFFFFFFFFu, mx, o));
    }
    if ((tid & 31) == 0) s_red[tid >> 5] = mn;
    __syncthreads();
    if (tid < 32) {
        float v = s_red[tid];
        for (int o = 16; o; o >>= 1) v = fminf(v, __shfl_down_sync(0xFFFFFFFFu, v, o));
        if (tid == 0) s_mn = v;
    }
    __syncthreads();
    if ((tid & 31) == 0) s_red[tid >> 5] = mx;
    __syncthreads();
    if (tid < 32) {
        float v = s_red[tid];
        for (int o = 16; o; o >>= 1) v = fmaxf(v, __shfl_down_sync(0xFFFFFFFFu, v, o));
        if (tid == 0) s_mx = v;
    }
    __syncthreads();
    const float mnv = s_mn, mxv = s_mx;
    if (mnv == mxv) { if (tid == 0) g_med[ch] = mnv + 0.2f; return; }

    // ---- fine histogram over candidates ----
    for (int i = tid; i < 8192; i += 1024) fh[i] = 0;
    __syncthreads();
    const float scale = 8192.0f / (mxv - mnv);
    for (int i = tid; i < n; i += 1024) {
        int b = (int)((c[i] - mnv) * scale);
        b = b < 0 ? 0 : (b > 8191 ? 8191 : b);
        atomicAdd(&fh[b], 1u);
    }
    __syncthreads();
    unsigned loc[8];
    unsigned s = 0;
    #pragma unroll
    for (int j = 0; j < 8; j++) { loc[j] = fh[tid * 8 + j]; s += loc[j]; }
    unsigned pref = block_excl_scan_1024(s);
    if (pref <= (unsigned)k2 && (unsigned)k2 < pref + s) {
        unsigned cum = pref;
        #pragma unroll
        for (int j = 0; j < 8; j++) {
            unsigned cc = loc[j];
            if (cum + cc > (unsigned)k2) { s_fb = tid * 8 + j; s_r2 = (int)(k2 - cum); break; }
            cum += cc;
        }
    }
    if (tid == 0) mcount = 0;
    __syncthreads();
    const int fb = s_fb, r2 = s_r2;
    for (int i = tid; i < n; i += 1024) {
        int b = (int)((c[i] - mnv) * scale);
        b = b < 0 ? 0 : (b > 8191 ? 8191 : b);
        if (b == fb) {
            int pp = atomicAdd(&mcount, 1);
            if (pp < 512) mem[pp] = c[i];
        }
    }
    __syncthreads();
    int m = mcount < 512 ? mcount : 512;
    for (int i = tid; i < m; i += 1024) {
        float vi = mem[i];
        int r = 0;
        for (int j = 0; j < m; j++) {
            float vj = mem[j];
            r += (vj < vi) || (vj == vi && j < i);
        }
        if (r == r2) g_med[ch] = vi + 0.2f;
    }
}

// ---------------------------------------------------------------------------
// launch #4 (profiled slot): separable conv 64x64, 512 thr (r8-proven) with
// float2 sliding window in the horizontal pass; fused packed-u16 pct hist.
// ---------------------------------------------------------------------------
__global__ __launch_bounds__(CTHREADS)
void conv_kernel(const float* __restrict__ x, const float* __restrict__ mask) {
    extern __shared__ float dsm[];
    float*    s_in  = dsm;                         // CSH * CSH
    float*    s_tmp = dsm + CSH * CSH;             // CSH * CTX
    unsigned* s_h   = (unsigned*)(dsm + CSH * CSH + CSH * CTX);  // PB/2 packed
    __shared__ float s_k[FW];

    const int tid = threadIdx.x;
    const int ch = blockIdx.z;
    const int nb = ch / 3;
    const int bx = blockIdx.x * CTX, by = blockIdx.y * CTY;

    if (tid < FW) s_k[tid] = g_k1[tid];
    for (int i = tid; i < PB / 2; i += CTHREADS) s_h[i] = 0;

    const float* xc = x + (size_t)ch * HW;
    const float* mc = mask + (size_t)nb * HW;
    const float med = g_med[ch];

    for (int i = tid; i < CSH * CSH; i += CTHREADS) {
        int r = i / CSH, c = i % CSH;
        int gy = min(max(by - PAD + r, 0), 511);
        int gx = min(max(bx - PAD + c, 0), 511);
        float xv = xc[gy * W + gx];
        float mv = mc[gy * W + gx];
        s_in[r * CSH + c] = mv * xv + (1.0f - mv) * med;
    }
    __syncthreads();

    // horizontal pass: CSH rows x 8 groups of 8 outputs = 688 items.
    // float2 sliding window: base r*86 + g*8 is even -> every load is LDS.64.
    for (int item = tid; item < CSH * (CTX / 8); item += CTHREADS) {
        const int r = item >> 3, g = item & 7;
        const float* row = s_in + r * CSH + g * 8;
        float w[10], acc[8];
        #pragma unroll
        for (int i = 0; i < 5; i++) {
            float2 v = *(const float2*)(row + 2 * i);
            w[2 * i] = v.x; w[2 * i + 1] = v.y;
        }
        #pragma unroll
        for (int m = 0; m < 8; m++) acc[m] = 0.0f;
        #pragma unroll
        for (int tp = 0; tp < 11; tp++) {             // taps 2*tp, 2*tp+1 (0..21)
            const float k0 = s_k[2 * tp], k1v = s_k[2 * tp + 1];
            #pragma unroll
            for (int m = 0; m < 8; m++) acc[m] = fmaf(w[m], k0, acc[m]);
            #pragma unroll
            for (int m = 0; m < 8; m++) acc[m] = fmaf(w[m + 1], k1v, acc[m]);
            if (tp < 10) {                            // shift by 2, load next pair
                #pragma unroll
                for (int m = 0; m < 8; m++) w[m] = w[m + 2];
                float2 v = *(const float2*)(row + 2 * tp + 10);
                w[8] = v.x; w[9] = v.y;
            }
        }
        const float k22 = s_k[22];                    // final tap: row[22+m] = w[m+2]
        #pragma unroll
        for (int m = 0; m < 8; m++) acc[m] = fmaf(w[m + 2], k22, acc[m]);

        float* outp = s_tmp + r * CTX + g * 8;
        #pragma unroll
        for (int m = 0; m < 8; m++) outp[m] = acc[m];
    }
    __syncthreads();

    // vertical pass: 64 cols x 8 y-groups of 8 outputs = 512 items (1/thread)
    {
        const int xx = tid & 63, y0 = (tid >> 6) * 8;
        const float* col = s_tmp + y0 * CTX + xx;
        float w[8], acc[8];
        #pragma unroll
        for (int m = 0; m < 8; m++) { w[m] = col[m * CTX]; acc[m] = 0.0f; }
        #pragma unroll
        for (int t = 0; t < FW; t++) {
            const float kt = s_k[t];
            #pragma unroll
            for (int m = 0; m < 8; m++) acc[m] = fmaf(w[m], kt, acc[m]);
            if (t < FW - 1) {
                #pragma unroll
                for (int m = 0; m < 7; m++) w[m] = w[m + 1];
                w[7] = col[(t + 8) * CTX];
            }
        }
        float* rp = g_res + (size_t)ch * HW + (size_t)(by + y0) * W + bx + xx;
        #pragma unroll
        for (int m = 0; m < 8; m++) {
            float xp = s_in[(y0 + m + PAD) * CSH + (xx + PAD)];
            float rv = 4.0f * (xp - acc[m]);
            rp[m * W] = rv;
            int b = (int)(rv * 256.0f) + PB / 2;
            b = b < 0 ? 0 : (b > PB - 1 ? PB - 1 : b);
            atomicAdd(&s_h[b >> 1], 1u << ((b & 1) * 16));
        }
    }
    __syncthreads();

    // flush fused percentile histogram (unpack u16 pairs)
    unsigned* gh = g_phist + ch * PB;
    for (int i = tid; i < PB / 2; i += CTHREADS) {
        unsigned w = s_h[i];
        unsigned lo = w & 0xFFFFu, hi = w >> 16;
        if (lo) atomicAdd(&gh[2 * i], lo);
        if (hi) atomicAdd(&gh[2 * i + 1], hi);
    }
}

// ---------------------------------------------------------------------------
// launch #5: extract lo/hi percentiles, restore hist to zero
// ---------------------------------------------------------------------------
__global__ __launch_bounds__(1024)
void pct_scan() {
    const int ch = blockIdx.x, tid = threadIdx.x;
    unsigned* h = g_phist + ch * PB;
    unsigned loc[PB / 1024];
    unsigned s = 0;
    #pragma unroll
    for (int j = 0; j < PB / 1024; j++) { loc[j] = h[tid * (PB / 1024) + j]; s += loc[j]; }
    unsigned pref = block_excl_scan_1024(s);

    const double n1 = (double)(HW - 1);
    #pragma unroll
    for (int rsel = 0; rsel < 2; rsel++) {
        double pos = n1 * (rsel ? 0.97 : 0.03);
        unsigned k = (unsigned)pos;
        float fr = (float)(pos - (double)k);
        if (pref <= k && k < pref + s) {
            unsigned cum = pref;
            #pragma unroll
            for (int j = 0; j < PB / 1024; j++) {
                unsigned c = loc[j];
                int b = tid * (PB / 1024) + j;
                if (cum + c > k) {
                    float v = (float)(b - PB / 2) * (1.0f / 256.0f);
                    float v1 = v;
                    if (k + 1 >= cum + c) {               // next value in a later bin
                        int b2 = b + 1;
                        while (b2 < PB && h[b2] == 0) b2++;
                        if (b2 < PB) v1 = (float)(b2 - PB / 2) * (1.0f / 256.0f);
                    }
                    float out = v + fr * (v1 - v);
                    if (rsel) g_hi[ch] = out; else g_lo[ch] = out;
                    break;
                }
                cum += c;
            }
        }
    }
    __syncthreads();
    // restore histogram to zero for the next replay
    #pragma unroll
    for (int j = 0; j < PB / 1024; j++) h[tid * (PB / 1024) + j] = 0u;
}

// ---------------------------------------------------------------------------
// launch #6: normalize + mask
// ---------------------------------------------------------------------------
__global__ __launch_bounds__(512)
void final_kernel(const float* __restrict__ mask, float* __restrict__ out) {
    const int ch = blockIdx.y;
    const int nb = ch / 3;
    const int i = blockIdx.x * blockDim.x + threadIdx.x;   // float4 index
    const float lo = g_lo[ch], hi = g_hi[ch];
    const float inv = 1.0f / (hi - lo);
    float4 r = ((const float4*)(g_res + (size_t)ch * HW))[i];
    float4 m = ((const float4*)(mask + (size_t)nb * HW))[i];
    float4 o;
    o.x = (r.x - lo) * inv * m.x;
    o.y = (r.y - lo) * inv * m.y;
    o.z = (r.z - lo) * inv * m.z;
    o.w = (r.w - lo) * inv * m.w;
    ((float4*)out)[(size_t)ch * (HW / 4) + i] = o;
}

// ---------------------------------------------------------------------------
extern "C" void kernel_launch(void* const* d_in, const int* in_sizes, int n_in,
                              void* d_out, int out_size) {
    const float* x    = (const float*)d_in[0];
    const float* mask = (const float*)d_in[1];
    const float* kern = (const float*)d_in[2];
    float* out = (float*)d_out;

    cudaFuncSetAttribute(conv_kernel, cudaFuncAttributeMaxDynamicSharedMemorySize, CONV_SMEM);

    k1_prep<<<1, 32>>>(kern);
    med_count<<<NCH * SEG, 512>>>(x);
    med_sel<<<NCH, 1024>>>(x);
    conv_kernel<<<dim3(W / CTX, W / CTY, NCH), CTHREADS, CONV_SMEM>>>(x, mask);
    pct_scan<<<NCH, 1024>>>();
    final_kernel<<<dim3(HW / 4 / 512, NCH), 512>>>(mask, out);
}

// round 12
// speedup vs baseline: 1.4717x; 1.0336x over previous
#include <cuda_runtime.h>
#include <cfloat>

#define HW   (512*512)
#define W    512
#define NCH  48            // 16 batches * 3 channels
#define FW   23
#define PAD  11

#define PB   8192          // pct histogram bins: i=(int)(res*256)+4096, res in (-16,16)
#define CAP  16384         // median candidate capacity per channel
#define SEG  8             // data-pass blocks per channel
// median fast-path candidate window in value space: [-10/512, +10/512)
#define T_LO (-10.0f/512.0f)
#define T_HI ( 10.0f/512.0f)

// hconv: 4 full rows per block, 256 threads (1 sliding group of 8 per thread)
#define HROWS 4
#define HROWW (W + 2*PAD)          // 534
// vconv: 64x64 output tile, 512 threads (1 sliding group of 8 per thread)
#define VTX 64
#define VTY 64
#define VSH (VTY + 2*PAD)          // 86 rows of g_tmp
#define VCONV_SMEM ((VSH*VTX + PB/2) * 4)   // 22 KB tile + 16 KB packed hist

// scratch (no cudaMalloc allowed; zero-initialized at load, kernels restore zeros)
__device__ float    g_res[(size_t)NCH * HW];
__device__ float    g_tmp[(size_t)NCH * HW];
__device__ unsigned g_phist[NCH * PB];
__device__ float    g_cand[NCH * CAP];
__device__ int      g_ccount[NCH];
__device__ int      g_below[NCH];
__device__ float    g_med[NCH];
__device__ float    g_lo[NCH];
__device__ float    g_hi[NCH];
__device__ float    g_k1[FW];

// ---------------------------------------------------------------------------
// block-wide exclusive scan over 1024 threads (shuffle-based)
// ---------------------------------------------------------------------------
__device__ __forceinline__ unsigned block_excl_scan_1024(unsigned val) {
    __shared__ unsigned warpsum[32];
    const unsigned lane = threadIdx.x & 31, wid = threadIdx.x >> 5;
    unsigned s = val;
    #pragma unroll
    for (int o = 1; o < 32; o <<= 1) {
        unsigned t = __shfl_up_sync(0xFFFFFFFFu, s, o);
        if (lane >= o) s += t;
    }
    if (lane == 31) warpsum[wid] = s;
    __syncthreads();
    if (wid == 0) {
        unsigned w = warpsum[lane];
        #pragma unroll
        for (int o = 1; o < 32; o <<= 1) {
            unsigned t = __shfl_up_sync(0xFFFFFFFFu, w, o);
            if (lane >= o) w += t;
        }
        warpsum[lane] = w;
    }
    __syncthreads();
    unsigned wexcl = wid ? warpsum[wid - 1] : 0u;
    return wexcl + s - val;
}

__device__ __forceinline__ int med_bin(float v) {   // for fallback only
    int b = (int)floorf(fmaf(v, 512.0f, 4096.0f));
    return b < 0 ? 0 : (b > 8191 ? 8191 : b);
}

// ---------------------------------------------------------------------------
// launch #1 (tiny): k1 = row sums of 2D gaussian kernel
// ---------------------------------------------------------------------------
__global__ void k1_prep(const float* __restrict__ kern) {
    int i = threadIdx.x;
    if (i < FW) {
        float s = 0.0f;
        for (int j = 0; j < FW; j++) s += kern[i * FW + j];
        g_k1[i] = s;
    }
}

// ---------------------------------------------------------------------------
// launch #2: count values below window + collect window candidates
// ---------------------------------------------------------------------------
__global__ __launch_bounds__(512)
void med_count(const float* __restrict__ x) {
    const int ch = blockIdx.x / SEG, seg = blockIdx.x % SEG;
    const int tid = threadIdx.x;
    const float4* p = (const float4*)(x + (size_t)ch * HW) + (size_t)seg * (HW / 4 / SEG);
    int below = 0;
    for (int i = tid; i < HW / 4 / SEG; i += 512) {
        float4 v = p[i];
        float vv[4] = { v.x, v.y, v.z, v.w };
        #pragma unroll
        for (int j = 0; j < 4; j++) {
            float f = vv[j];
            below += (f < T_LO);
            if (f >= T_LO && f < T_HI) {
                int pp = atomicAdd(&g_ccount[ch], 1);
                if (pp < CAP) g_cand[ch * CAP + pp] = f;
            }
        }
    }
    for (int o = 16; o; o >>= 1) below += __shfl_down_sync(0xFFFFFFFFu, below, o);
    if ((tid & 31) == 0 && below) atomicAdd(&g_below[ch], below);
}

// ---------------------------------------------------------------------------
// launch #3: exact median selection (fast path via window; exact fallback)
// ---------------------------------------------------------------------------
__global__ __launch_bounds__(1024)
void med_sel(const float* __restrict__ x) {
    const int ch = blockIdx.x, tid = threadIdx.x;
    __shared__ unsigned fh[8192];
    __shared__ float s_red[32];
    __shared__ float s_mn, s_mx;
    __shared__ int s_fb, s_r2, s_n, s_k2;
    __shared__ int s_cnt;
    __shared__ float mem[512];
    __shared__ int mcount;

    const int k = (HW - 1) / 2;
    int below = g_below[ch];
    int cnt   = g_ccount[ch];
    __syncthreads();
    if (tid == 0) {
        g_below[ch] = 0;
        g_ccount[ch] = 0;
        s_cnt = 0;
    }
    const bool fast = (below <= k) && (k < below + cnt) && (cnt <= CAP);

    if (fast) {
        if (tid == 0) { s_n = cnt; s_k2 = k - below; }
        __syncthreads();
    } else {
        for (int i = tid; i < 8192; i += 1024) fh[i] = 0;
        __syncthreads();
        const float4* p = (const float4*)(x + (size_t)ch * HW);
        for (int i = tid; i < HW / 4; i += 1024) {
            float4 v = p[i];
            atomicAdd(&fh[med_bin(v.x)], 1u);
            atomicAdd(&fh[med_bin(v.y)], 1u);
            atomicAdd(&fh[med_bin(v.z)], 1u);
            atomicAdd(&fh[med_bin(v.w)], 1u);
        }
        __syncthreads();
        unsigned loc[8];
        unsigned s = 0;
        #pragma unroll
        for (int j = 0; j < 8; j++) { loc[j] = fh[tid * 8 + j]; s += loc[j]; }
        unsigned pref = block_excl_scan_1024(s);
        __shared__ int s_selbin;
        if (pref <= (unsigned)k && (unsigned)k < pref + s) {
            unsigned cum = pref;
            #pragma unroll
            for (int j = 0; j < 8; j++) {
                unsigned c = loc[j];
                if (cum + c > (unsigned)k) { s_selbin = tid * 8 + j; s_k2 = (int)(k - cum); break; }
                cum += c;
            }
        }
        __syncthreads();
        const int sb = s_selbin;
        for (int i = tid; i < HW / 4; i += 1024) {
            float4 v = p[i];
            float vv[4] = { v.x, v.y, v.z, v.w };
            #pragma unroll
            for (int j = 0; j < 4; j++) {
                if (med_bin(vv[j]) == sb) {
                    int pp = atomicAdd(&s_cnt, 1);
                    if (pp < CAP) g_cand[ch * CAP + pp] = vv[j];
                }
            }
        }
        __syncthreads();
        if (tid == 0) s_n = s_cnt < CAP ? s_cnt : CAP;
        __syncthreads();
    }

    const int n = s_n, k2 = s_k2;
    const float* c = g_cand + ch * CAP;

    float mn = FLT_MAX, mx = -FLT_MAX;
    for (int i = tid; i < n; i += 1024) {
        float v = c[i];
        mn = fminf(mn, v); mx = fmaxf(mx, v);
    }
    for (int o = 16; o; o >>= 1) {
        mn = fminf(mn, __shfl_down_sync(0xFFFFFFFFu, mn, o));
        mx = fmaxf(mx, __shfl_down_sync(0xFFFFFFFFu, mx, o));
    }
    if ((tid & 31) == 0) s_red[tid >> 5] = mn;
    __syncthreads();
    if (tid < 32) {
        float v = s_red[tid];
        for (int o = 16; o; o >>= 1) v = fminf(v, __shfl_down_sync(0xFFFFFFFFu, v, o));
        if (tid == 0) s_mn = v;
    }
    __syncthreads();
    if ((tid & 31) == 0) s_red[tid >> 5] = mx;
    __syncthreads();
    if (tid < 32) {
        float v = s_red[tid];
        for (int o = 16; o; o >>= 1) v = fmaxf(v, __shfl_down_sync(0xFFFFFFFFu, v, o));
        if (tid == 0) s_mx = v;
    }
    __syncthreads();
    const float mnv = s_mn, mxv = s_mx;
    if (mnv == mxv) { if (tid == 0) g_med[ch] = mnv + 0.2f; return; }

    for (int i = tid; i < 8192; i += 1024) fh[i] = 0;
    __syncthreads();
    const float scale = 8192.0f / (mxv - mnv);
    for (int i = tid; i < n; i += 1024) {
        int b = (int)((c[i] - mnv) * scale);
        b = b < 0 ? 0 : (b > 8191 ? 8191 : b);
        atomicAdd(&fh[b], 1u);
    }
    __syncthreads();
    unsigned loc[8];
    unsigned s = 0;
    #pragma unroll
    for (int j = 0; j < 8; j++) { loc[j] = fh[tid * 8 + j]; s += loc[j]; }
    unsigned pref = block_excl_scan_1024(s);
    if (pref <= (unsigned)k2 && (unsigned)k2 < pref + s) {
        unsigned cum = pref;
        #pragma unroll
        for (int j = 0; j < 8; j++) {
            unsigned cc = loc[j];
            if (cum + cc > (unsigned)k2) { s_fb = tid * 8 + j; s_r2 = (int)(k2 - cum); break; }
            cum += cc;
        }
    }
    if (tid == 0) mcount = 0;
    __syncthreads();
    const int fb = s_fb, r2 = s_r2;
    for (int i = tid; i < n; i += 1024) {
        int b = (int)((c[i] - mnv) * scale);
        b = b < 0 ? 0 : (b > 8191 ? 8191 : b);
        if (b == fb) {
            int pp = atomicAdd(&mcount, 1);
            if (pp < 512) mem[pp] = c[i];
        }
    }
    __syncthreads();
    int m = mcount < 512 ? mcount : 512;
    for (int i = tid; i < m; i += 1024) {
        float vi = mem[i];
        int r = 0;
        for (int j = 0; j < m; j++) {
            float vj = mem[j];
            r += (vj < vi) || (vj == vi && j < i);
        }
        if (r == r2) g_med[ch] = vi + 0.2f;
    }
}

// ---------------------------------------------------------------------------
// launch #4: horizontal conv pass — 4 full rows/block, xp fused, balanced
// ---------------------------------------------------------------------------
__global__ __launch_bounds__(256)
void hconv(const float* __restrict__ x, const float* __restrict__ mask) {
    __shared__ float xp[HROWS][HROWW];                // 4 x 534 floats = 8.5 KB
    __shared__ float s_k[FW];
    const int tid = threadIdx.x;
    const int ch = blockIdx.y;
    const int nb = ch / 3;
    const int row0 = blockIdx.x * HROWS;

    if (tid < FW) s_k[tid] = g_k1[tid];

    const float* xc = x + (size_t)ch * HW;
    const float* mc = mask + (size_t)nb * HW;
    const float med = g_med[ch];

    for (int i = tid; i < HROWS * HROWW; i += 256) {
        int r = i / HROWW, cc = i % HROWW;
        int gc = min(max(cc - PAD, 0), W - 1);
        float xv = xc[(row0 + r) * W + gc];
        float mv = mc[(row0 + r) * W + gc];
        xp[r][cc] = mv * xv + (1.0f - mv) * med;
    }
    __syncthreads();

    // one sliding group of 8 outputs per thread (float2 window)
    const int r = tid >> 6, g = tid & 63;
    const float* rowp = xp[r] + g * 8;                // xp idx c..c+29 for outs c..c+7
    float w[10], acc[8];
    #pragma unroll
    for (int i = 0; i < 5; i++) {
        float2 v = *(const float2*)(rowp + 2 * i);
        w[2 * i] = v.x; w[2 * i + 1] = v.y;
    }
    #pragma unroll
    for (int m = 0; m < 8; m++) acc[m] = 0.0f;
    #pragma unroll
    for (int tp = 0; tp < 11; tp++) {
        const float k0 = s_k[2 * tp], k1v = s_k[2 * tp + 1];
        #pragma unroll
        for (int m = 0; m < 8; m++) acc[m] = fmaf(w[m], k0, acc[m]);
        #pragma unroll
        for (int m = 0; m < 8; m++) acc[m] = fmaf(w[m + 1], k1v, acc[m]);
        if (tp < 10) {
            #pragma unroll
            for (int m = 0; m < 8; m++) w[m] = w[m + 2];
            float2 v = *(const float2*)(rowp + 2 * tp + 10);
            w[8] = v.x; w[9] = v.y;
        }
    }
    const float k22 = s_k[22];
    #pragma unroll
    for (int m = 0; m < 8; m++) acc[m] = fmaf(w[m + 2], k22, acc[m]);

    float4* outp = (float4*)(g_tmp + (size_t)ch * HW + (size_t)(row0 + r) * W + g * 8);
    outp[0] = make_float4(acc[0], acc[1], acc[2], acc[3]);
    outp[1] = make_float4(acc[4], acc[5], acc[6], acc[7]);
}

// ---------------------------------------------------------------------------
// launch #5: vertical conv pass + res + fused packed-u16 pct hist
// 64x64 tile, 512 threads, 1 sliding group per thread, 38.4 KB smem
// ---------------------------------------------------------------------------
__global__ __launch_bounds__(512)
void vconv(const float* __restrict__ x, const float* __restrict__ mask) {
    extern __shared__ float dsm[];
    float*    st  = dsm;                              // VSH x VTX g_tmp tile
    unsigned* s_h = (unsigned*)(dsm + VSH * VTX);     // PB/2 packed hist
    __shared__ float s_k[FW];

    const int tid = threadIdx.x;
    const int ch = blockIdx.z;
    const int nb = ch / 3;
    const int bx = blockIdx.x * VTX, by = blockIdx.y * VTY;

    if (tid < FW) s_k[tid] = g_k1[tid];
    for (int i = tid; i < PB / 2; i += 512) s_h[i] = 0;

    const float* tc = g_tmp + (size_t)ch * HW;
    for (int i = tid; i < VSH * VTX; i += 512) {
        int r = i >> 6, c = i & 63;
        int gy = min(max(by - PAD + r, 0), 511);
        st[r * VTX + c] = tc[gy * W + bx + c];
    }
    __syncthreads();

    // vertical sliding window: 1 group of 8 outputs per thread
    const int xx = tid & 63, y0 = (tid >> 6) * 8;
    const float* col = st + y0 * VTX + xx;
    float w[8], acc[8];
    #pragma unroll
    for (int m = 0; m < 8; m++) { w[m] = col[m * VTX]; acc[m] = 0.0f; }
    #pragma unroll
    for (int t = 0; t < FW; t++) {
        const float kt = s_k[t];
        #pragma unroll
        for (int m = 0; m < 8; m++) acc[m] = fmaf(w[m], kt, acc[m]);
        if (t < FW - 1) {
            #pragma unroll
            for (int m = 0; m < 7; m++) w[m] = w[m + 1];
            w[7] = col[(t + 8) * VTX];
        }
    }

    const float* xc = x + (size_t)ch * HW;
    const float* mc = mask + (size_t)nb * HW;
    const float med = g_med[ch];
    float* rp = g_res + (size_t)ch * HW + (size_t)(by + y0) * W + bx + xx;
    #pragma unroll
    for (int m = 0; m < 8; m++) {
        const int gi = (by + y0 + m) * W + bx + xx;
        float mv = mc[gi];
        float xpv = mv * xc[gi] + (1.0f - mv) * med;
        float rv = 4.0f * (xpv - acc[m]);
        rp[m * W] = rv;
        int b = (int)(rv * 256.0f) + PB / 2;
        b = b < 0 ? 0 : (b > PB - 1 ? PB - 1 : b);
        atomicAdd(&s_h[b >> 1], 1u << ((b & 1) * 16));
    }
    __syncthreads();

    unsigned* gh = g_phist + ch * PB;
    for (int i = tid; i < PB / 2; i += 512) {
        unsigned w2 = s_h[i];
        unsigned lo = w2 & 0xFFFFu, hi = w2 >> 16;
        if (lo) atomicAdd(&gh[2 * i], lo);
        if (hi) atomicAdd(&gh[2 * i + 1], hi);
    }
}

// ---------------------------------------------------------------------------
// launch #6: extract lo/hi percentiles, restore hist to zero
// ---------------------------------------------------------------------------
__global__ __launch_bounds__(1024)
void pct_scan() {
    const int ch = blockIdx.x, tid = threadIdx.x;
    unsigned* h = g_phist + ch * PB;
    unsigned loc[PB / 1024];
    unsigned s = 0;
    #pragma unroll
    for (int j = 0; j < PB / 1024; j++) { loc[j] = h[tid * (PB / 1024) + j]; s += loc[j]; }
    unsigned pref = block_excl_scan_1024(s);

    const double n1 = (double)(HW - 1);
    #pragma unroll
    for (int rsel = 0; rsel < 2; rsel++) {
        double pos = n1 * (rsel ? 0.97 : 0.03);
        unsigned k = (unsigned)pos;
        float fr = (float)(pos - (double)k);
        if (pref <= k && k < pref + s) {
            unsigned cum = pref;
            #pragma unroll
            for (int j = 0; j < PB / 1024; j++) {
                unsigned c = loc[j];
                int b = tid * (PB / 1024) + j;
                if (cum + c > k) {
                    float v = (float)(b - PB / 2) * (1.0f / 256.0f);
                    float v1 = v;
                    if (k + 1 >= cum + c) {
                        int b2 = b + 1;
                        while (b2 < PB && h[b2] == 0) b2++;
                        if (b2 < PB) v1 = (float)(b2 - PB / 2) * (1.0f / 256.0f);
                    }
                    float out = v + fr * (v1 - v);
                    if (rsel) g_hi[ch] = out; else g_lo[ch] = out;
                    break;
                }
                cum += c;
            }
        }
    }
    __syncthreads();
    #pragma unroll
    for (int j = 0; j < PB / 1024; j++) h[tid * (PB / 1024) + j] = 0u;
}

// ---------------------------------------------------------------------------
// launch #7: normalize + mask
// ---------------------------------------------------------------------------
__global__ __launch_bounds__(512)
void final_kernel(const float* __restrict__ mask, float* __restrict__ out) {
    const int ch = blockIdx.y;
    const int nb = ch / 3;
    const int i = blockIdx.x * blockDim.x + threadIdx.x;
    const float lo = g_lo[ch], hi = g_hi[ch];
    const float inv = 1.0f / (hi - lo);
    float4 r = ((const float4*)(g_res + (size_t)ch * HW))[i];
    float4 m = ((const float4*)(mask + (size_t)nb * HW))[i];
    float4 o;
    o.x = (r.x - lo) * inv * m.x;
    o.y = (r.y - lo) * inv * m.y;
    o.z = (r.z - lo) * inv * m.z;
    o.w = (r.w - lo) * inv * m.w;
    ((float4*)out)[(size_t)ch * (HW / 4) + i] = o;
}

// ---------------------------------------------------------------------------
extern "C" void kernel_launch(void* const* d_in, const int* in_sizes, int n_in,
                              void* d_out, int out_size) {
    const float* x    = (const float*)d_in[0];
    const float* mask = (const float*)d_in[1];
    const float* kern = (const float*)d_in[2];
    float* out = (float*)d_out;

    cudaFuncSetAttribute(vconv, cudaFuncAttributeMaxDynamicSharedMemorySize, VCONV_SMEM);

    k1_prep<<<1, 32>>>(kern);
    med_count<<<NCH * SEG, 512>>>(x);
    med_sel<<<NCH, 1024>>>(x);
    hconv<<<dim3(W / HROWS, NCH), 256>>>(x, mask);
    vconv<<<dim3(W / VTX, W / VTY, NCH), 512, VCONV_SMEM>>>(x, mask);
    pct_scan<<<NCH, 1024>>>();
    final_kernel<<<dim3(HW / 4 / 512, NCH), 512>>>(mask, out);
}